// round 12
// baseline (speedup 1.0000x reference)
#include <cuda_runtime.h>
#include <mma.h>
#include <cstdint>

using namespace nvcuda;

// Problem constants
#define T_TOK 1024
#define H_DIM 2048
#define F_DIM 1408
#define N_EXP 16
#define K_TOP 6

// Tiling: BM=128, BN=128, BK=32; 16 warps as 4m x 4n, warp tile 32x32; 2 CTAs/SM
#define BM 128
#define BN 128
#define BK 32
#define NTHR 512
#define LDS 36                       // smem leading dim (floats)
#define NSTAGE 3
#define STG_FLOATS ((BM + BN) * LDS)               // 9216 floats = 36864 B
#define SMEM_BYTES (NSTAGE * STG_FLOATS * (int)sizeof(float))   // 110592 B
#define LDSTG 132                    // epilogue stage leading dim (128 + pad)

// ---------------- device scratch ----------------
__device__ int   g_counts[N_EXP];
__device__ int   g_tokens[N_EXP * T_TOK];
__device__ float g_slotw[N_EXP * T_TOK];
__device__ float g_xr[(size_t)T_TOK * H_DIM];             // tf32-rounded x
__device__ float g_act[(size_t)N_EXP * T_TOK * F_DIM];    // tf32-rounded act

// ---------------- wmma typedefs ----------------
typedef wmma::fragment<wmma::matrix_a, 16, 16, 8, wmma::precision::tf32, wmma::row_major> FragA;
typedef wmma::fragment<wmma::matrix_b, 16, 16, 8, wmma::precision::tf32, wmma::col_major> FragB;
typedef wmma::fragment<wmma::accumulator, 16, 16, 8, float> FragC;

template <class F>
__device__ __forceinline__ void to_tf32(F& f) {
#pragma unroll
    for (int i = 0; i < f.num_elements; i++) f.x[i] = wmma::__float_to_tf32(f.x[i]);
}

__device__ __forceinline__ float rntf(float v) {
    asm("cvt.rna.tf32.f32 %0, %1;" : "=f"(v) : "f"(v));
    return v;
}

// ---------------- cp.async helpers ----------------
__device__ __forceinline__ void cp16(void* dst, const float* src) {
    uint32_t d = (uint32_t)__cvta_generic_to_shared(dst);
    asm volatile("cp.async.cg.shared.global [%0], [%1], 16;" :: "r"(d), "l"(src));
}
#define CP_COMMIT() asm volatile("cp.async.commit_group;")
#define CP_WAIT1()  asm volatile("cp.async.wait_group 1;")
#define CP_WAIT0()  asm volatile("cp.async.wait_group 0;")

// ---------------- init + prepass ----------------
__global__ void init_kernel() {
    if (threadIdx.x < N_EXP) g_counts[threadIdx.x] = 0;
}

__global__ __launch_bounds__(256) void round_x_kernel(const float* __restrict__ x) {
    int idx = blockIdx.x * 256 + threadIdx.x;   // float4 index
    if (idx < T_TOK * H_DIM / 4) {
        float4 v = ((const float4*)x)[idx];
        v.x = rntf(v.x); v.y = rntf(v.y); v.z = rntf(v.z); v.w = rntf(v.w);
        ((float4*)g_xr)[idx] = v;
    }
}

// ---------------- router ----------------
__global__ __launch_bounds__(256) void router_kernel(const float* __restrict__ x,
                                                     const float* __restrict__ gw) {
    int t = blockIdx.x;
    __shared__ float slog[N_EXP];
    if (threadIdx.x < N_EXP) slog[threadIdx.x] = 0.f;
    __syncthreads();

    const float* xr = x + (size_t)t * H_DIM;
    float part[N_EXP];
#pragma unroll
    for (int e = 0; e < N_EXP; e++) part[e] = 0.f;

    for (int h = threadIdx.x; h < H_DIM; h += 256) {
        float xv = xr[h];
#pragma unroll
        for (int e = 0; e < N_EXP; e++) part[e] += xv * gw[e * H_DIM + h];
    }
#pragma unroll
    for (int e = 0; e < N_EXP; e++) {
#pragma unroll
        for (int off = 16; off; off >>= 1)
            part[e] += __shfl_down_sync(0xFFFFFFFFu, part[e], off);
    }
    if ((threadIdx.x & 31) == 0) {
#pragma unroll
        for (int e = 0; e < N_EXP; e++) atomicAdd(&slog[e], part[e]);
    }
    __syncthreads();

    if (threadIdx.x == 0) {
        float mx = -1e30f;
#pragma unroll
        for (int e = 0; e < N_EXP; e++) mx = fmaxf(mx, slog[e]);
        float p[N_EXP]; float s = 0.f;
#pragma unroll
        for (int e = 0; e < N_EXP; e++) { p[e] = __expf(slog[e] - mx); s += p[e]; }
        float inv = 1.f / s;
#pragma unroll
        for (int e = 0; e < N_EXP; e++) p[e] *= inv;

        int sel[K_TOP]; float wv[K_TOP]; float ws = 0.f;
        bool used[N_EXP];
#pragma unroll
        for (int e = 0; e < N_EXP; e++) used[e] = false;
#pragma unroll
        for (int k = 0; k < K_TOP; k++) {
            int best = -1; float bv = -1.f;
#pragma unroll
            for (int e = 0; e < N_EXP; e++)
                if (!used[e] && p[e] > bv) { bv = p[e]; best = e; }
            used[best] = true; sel[k] = best; wv[k] = bv; ws += bv;
        }
        float wsi = 1.f / ws;
#pragma unroll
        for (int k = 0; k < K_TOP; k++) {
            int e = sel[k];
            int pos = atomicAdd(&g_counts[e], 1);
            g_tokens[e * T_TOK + pos] = t;
            g_slotw[e * T_TOK + pos] = wv[k] * wsi;
        }
    }
}

// Inner product over one BK=32 tile; warp tile 32x32 (2m x 2n fragments).
// A is pre-rounded (no cvt); B gets cvt inline. No manual pipelining (ptxas does it).
__device__ __forceinline__ void tile_mma(const float* sA, const float* sB,
                                         int wm, int wn, FragC acc[2][2]) {
#pragma unroll
    for (int ks = 0; ks < BK; ks += 8) {
        FragA a0, a1;
        wmma::load_matrix_sync(a0, sA + (wm * 32) * LDS + ks, LDS);
        wmma::load_matrix_sync(a1, sA + (wm * 32 + 16) * LDS + ks, LDS);
#pragma unroll
        for (int j = 0; j < 2; j++) {
            FragB b;
            wmma::load_matrix_sync(b, sB + (wn * 32 + j * 16) * LDS + ks, LDS);
            to_tf32(b);
            wmma::mma_sync(acc[0][j], a0, b, acc[0][j]);
            wmma::mma_sync(acc[1][j], a1, b, acc[1][j]);
        }
    }
}

// ============ GEMM1: gathered g_xr @ [gate||up]^T, fused SiLU, 3-stage cp.async ============
// grid (T/128=8 m FASTEST, F/64=22, 16); 512 thr, 16 warps 4m x 4n, warp 32x32
__global__ __launch_bounds__(NTHR, 2) void gemm1_kernel(const float* __restrict__ wv1) {
    extern __shared__ float smem[];
    __shared__ int stok[BM];

    int e = blockIdx.z;
    int ne = g_counts[e];
    int m0 = blockIdx.x * BM;
    if (m0 >= ne) return;
    int n0 = blockIdx.y * 64;      // f-slice of 64 (B rows: 64 gate + 64 up)

    int tid = threadIdx.x;
    int wid = tid >> 5;
    int wm = wid >> 2;             // 0..3
    int wn = wid & 3;              // 0..3

    for (int i = tid; i < BM; i += NTHR) {
        int gi = m0 + i;
        stok[i] = (gi < ne) ? g_tokens[e * T_TOK + gi] : g_tokens[e * T_TOK + m0];
    }
    __syncthreads();

    // producers: A 2 float4/thread, B 2 float4/thread
    const float* pA[2]; uint32_t oA[2];
#pragma unroll
    for (int j = 0; j < 2; j++) {
        int idx = tid + j * NTHR, r = idx >> 3, c = (idx & 7) * 4;
        oA[j] = r * LDS + c;
        pA[j] = g_xr + (size_t)stok[r] * H_DIM + c;
    }
    const float* pB[2]; uint32_t oB[2];
#pragma unroll
    for (int j = 0; j < 2; j++) {
        int idx = tid + j * NTHR, r = idx >> 3, c = (idx & 7) * 4;
        oB[j] = BM * LDS + r * LDS + c;
        size_t row = (r < 64) ? ((size_t)e * 2 * F_DIM + n0 + r)
                              : ((size_t)e * 2 * F_DIM + F_DIM + n0 + (r - 64));
        pB[j] = wv1 + row * H_DIM + c;
    }

#define G1_ISSUE(s) do {                                        \
    float* st_ = smem + (s) * STG_FLOATS;                       \
    _Pragma("unroll")                                           \
    for (int j_ = 0; j_ < 2; j_++) { cp16(st_ + oA[j_], pA[j_]); pA[j_] += BK; } \
    _Pragma("unroll")                                           \
    for (int j_ = 0; j_ < 2; j_++) { cp16(st_ + oB[j_], pB[j_]); pB[j_] += BK; } \
    CP_COMMIT();                                                \
} while (0)

    FragC acc[2][2];
#pragma unroll
    for (int i = 0; i < 2; i++)
#pragma unroll
        for (int j = 0; j < 2; j++) wmma::fill_fragment(acc[i][j], 0.f);

    const int NT = H_DIM / BK;     // 64
    G1_ISSUE(0);
    G1_ISSUE(1);

    int scons = 0, sprod = 2;      // rotating stage indices (no div)
    for (int it = 0; it < NT; ++it) {
        if (it + 1 < NT) CP_WAIT1(); else CP_WAIT0();
        __syncthreads();
        if (it + 2 < NT) G1_ISSUE(sprod);
        if (++sprod == NSTAGE) sprod = 0;

        float* sA = smem + scons * STG_FLOATS;
        if (++scons == NSTAGE) scons = 0;
        tile_mma(sA, sA + BM * LDS, wm, wn, acc);
    }
#undef G1_ISSUE

    // epilogue: stage 128x132 (cols 0..63 gate, 64..127 up), fused SiLU -> g_act
    __syncthreads();
    float* stage = smem;
#pragma unroll
    for (int i = 0; i < 2; i++)
#pragma unroll
        for (int j = 0; j < 2; j++)
            wmma::store_matrix_sync(stage + (wm * 32 + i * 16) * LDSTG + wn * 32 + j * 16,
                                    acc[i][j], LDSTG, wmma::mem_row_major);
    __syncthreads();

    for (int q = tid; q < BM * 16; q += NTHR) {
        int r = q >> 4, c = (q & 15) * 4;   // gate cols 0..60
        int gr = m0 + r;
        if (gr < ne) {
            float4 g = *(float4*)(stage + r * LDSTG + c);
            float4 u = *(float4*)(stage + r * LDSTG + 64 + c);
            float4 o;
            o.x = rntf((g.x / (1.f + __expf(-g.x))) * u.x);
            o.y = rntf((g.y / (1.f + __expf(-g.y))) * u.y);
            o.z = rntf((g.z / (1.f + __expf(-g.z))) * u.z);
            o.w = rntf((g.w / (1.f + __expf(-g.w))) * u.w);
            *(float4*)(g_act + ((size_t)e * T_TOK + gr) * F_DIM + n0 + c) = o;
        }
    }
}

// ============ GEMM2: g_act @ w2^T, fused weighted atomic combine, 3-stage ============
// grid (T/128=8 m FASTEST, H/128=16, 16); 512 thr, 16 warps 4m x 4n, warp 32x32
__global__ __launch_bounds__(NTHR, 2) void gemm2_kernel(const float* __restrict__ w2,
                                                        float* __restrict__ out) {
    extern __shared__ float smem[];
    __shared__ int   stok[BM];
    __shared__ float swt[BM];

    int e = blockIdx.z;
    int ne = g_counts[e];
    int m0 = blockIdx.x * BM;
    if (m0 >= ne) return;
    int n0 = blockIdx.y * BN;

    int tid = threadIdx.x;
    int wid = tid >> 5;
    int wm = wid >> 2;
    int wn = wid & 3;
    int nrows = ne - m0;

    for (int i = tid; i < BM; i += NTHR) {
        bool ok = (m0 + i < ne);
        stok[i] = ok ? g_tokens[e * T_TOK + m0 + i] : 0;
        swt[i]  = ok ? g_slotw[e * T_TOK + m0 + i] : 0.f;
    }
    __syncthreads();

    const float* pA[2]; uint32_t oA[2];
#pragma unroll
    for (int j = 0; j < 2; j++) {
        int idx = tid + j * NTHR, r = idx >> 3, c = (idx & 7) * 4;
        oA[j] = r * LDS + c;
        int rr = (r < nrows) ? r : 0;
        pA[j] = g_act + ((size_t)e * T_TOK + m0 + rr) * F_DIM + c;
    }
    const float* pB[2]; uint32_t oB[2];
#pragma unroll
    for (int j = 0; j < 2; j++) {
        int idx = tid + j * NTHR, r = idx >> 3, c = (idx & 7) * 4;
        oB[j] = BM * LDS + r * LDS + c;
        pB[j] = w2 + ((size_t)e * H_DIM + n0 + r) * F_DIM + c;
    }

#define G2_ISSUE(s) do {                                        \
    float* st_ = smem + (s) * STG_FLOATS;                       \
    _Pragma("unroll")                                           \
    for (int j_ = 0; j_ < 2; j_++) { cp16(st_ + oA[j_], pA[j_]); pA[j_] += BK; } \
    _Pragma("unroll")                                           \
    for (int j_ = 0; j_ < 2; j_++) { cp16(st_ + oB[j_], pB[j_]); pB[j_] += BK; } \
    CP_COMMIT();                                                \
} while (0)

    FragC acc[2][2];
#pragma unroll
    for (int i = 0; i < 2; i++)
#pragma unroll
        for (int j = 0; j < 2; j++) wmma::fill_fragment(acc[i][j], 0.f);

    const int NT = F_DIM / BK;     // 44
    G2_ISSUE(0);
    G2_ISSUE(1);

    int scons = 0, sprod = 2;
    for (int it = 0; it < NT; ++it) {
        if (it + 1 < NT) CP_WAIT1(); else CP_WAIT0();
        __syncthreads();
        if (it + 2 < NT) G2_ISSUE(sprod);
        if (++sprod == NSTAGE) sprod = 0;

        float* sA = smem + scons * STG_FLOATS;
        if (++scons == NSTAGE) scons = 0;
        tile_mma(sA, sA + BM * LDS, wm, wn, acc);
    }
#undef G2_ISSUE

    // epilogue: stage 128x132, weighted atomic scatter to out[t, h]
    __syncthreads();
    float* stage = smem;
#pragma unroll
    for (int i = 0; i < 2; i++)
#pragma unroll
        for (int j = 0; j < 2; j++)
            wmma::store_matrix_sync(stage + (wm * 32 + i * 16) * LDSTG + wn * 32 + j * 16,
                                    acc[i][j], LDSTG, wmma::mem_row_major);
    __syncthreads();

    for (int idx = tid; idx < BM * 32; idx += NTHR) {
        int r = idx >> 5, cc = (idx & 31) * 4;
        if (r < nrows) {
            int t = stok[r];
            float w = swt[r];
            float4 v = *(float4*)(stage + r * LDSTG + cc);
            float* o = out + (size_t)t * H_DIM + n0 + cc;
            atomicAdd(o + 0, w * v.x);
            atomicAdd(o + 1, w * v.y);
            atomicAdd(o + 2, w * v.z);
            atomicAdd(o + 3, w * v.w);
        }
    }
}

// ---------------- launch ----------------
extern "C" void kernel_launch(void* const* d_in, const int* in_sizes, int n_in,
                              void* d_out, int out_size) {
    (void)in_sizes; (void)n_in;
    const float* x    = (const float*)d_in[0];
    const float* gw   = (const float*)d_in[1];
    const float* wv1  = (const float*)d_in[2];
    const float* w2   = (const float*)d_in[3];
    float* out = (float*)d_out;

    static bool attr_set = false;
    if (!attr_set) {
        cudaFuncSetAttribute(gemm1_kernel, cudaFuncAttributeMaxDynamicSharedMemorySize, SMEM_BYTES);
        cudaFuncSetAttribute(gemm2_kernel, cudaFuncAttributeMaxDynamicSharedMemorySize, SMEM_BYTES);
        attr_set = true;
    }

    cudaMemsetAsync(out, 0, (size_t)out_size * sizeof(float));
    init_kernel<<<1, 32>>>();
    round_x_kernel<<<(T_TOK * H_DIM / 4 + 255) / 256, 256>>>(x);
    router_kernel<<<T_TOK, 256>>>(x, gw);
    gemm1_kernel<<<dim3(T_TOK / BM, F_DIM / 64, N_EXP), NTHR, SMEM_BYTES>>>(wv1);
    gemm2_kernel<<<dim3(T_TOK / BM, H_DIM / BN, N_EXP), NTHR, SMEM_BYTES>>>(w2, out);
}

// round 13
// speedup vs baseline: 4.4291x; 4.4291x over previous
#include <cuda_runtime.h>
#include <cuda_fp16.h>
#include <mma.h>
#include <cstdint>

using namespace nvcuda;

// Problem constants
#define T_TOK 1024
#define H_DIM 2048
#define F_DIM 1408
#define N_EXP 16
#define K_TOP 6

// Tiling: BM=128, BN=128, BK=32 (halfs); 8 warps 2m x 4n, warp tile 64x32; 2 CTAs/SM
#define BM 128
#define BN 128
#define BK 32
#define NTHR 256
#define LDH 40                         // smem leading dim in halfs (32 + 8 pad; 80B rows)
#define NSTAGE 4
#define STG_HALFS ((BM + BN) * LDH)    // 10240 halfs = 20480 B per stage
#define SMEM_BYTES (NSTAGE * STG_HALFS * (int)sizeof(__half))   // 81920 B
#define LDSTG 132                      // fp32 epilogue stage leading dim

// ---------------- device scratch ----------------
__device__ int    g_counts[N_EXP];
__device__ int    g_tokens[N_EXP * T_TOK];
__device__ float  g_slotw[N_EXP * T_TOK];
__device__ __half g_xh[(size_t)T_TOK * H_DIM];              // half-rounded x
__device__ __half g_acth[(size_t)N_EXP * T_TOK * F_DIM];    // half activations

// ---------------- wmma typedefs (fp16 in, fp32 acc) ----------------
typedef wmma::fragment<wmma::matrix_a, 16, 16, 16, __half, wmma::row_major> FragA;
typedef wmma::fragment<wmma::matrix_b, 16, 16, 16, __half, wmma::col_major> FragB;
typedef wmma::fragment<wmma::accumulator, 16, 16, 16, float> FragC;

// ---------------- cp.async helpers ----------------
__device__ __forceinline__ void cp16(void* dst, const void* src) {
    uint32_t d = (uint32_t)__cvta_generic_to_shared(dst);
    asm volatile("cp.async.cg.shared.global [%0], [%1], 16;" :: "r"(d), "l"(src));
}
#define CP_COMMIT() asm volatile("cp.async.commit_group;")
#define CP_WAIT2()  asm volatile("cp.async.wait_group 2;")
#define CP_WAIT0()  asm volatile("cp.async.wait_group 0;")

// convert float4 -> 4 halfs packed in uint2
__device__ __forceinline__ uint2 f4_to_h4(float4 v) {
    __half2 h01 = __floats2half2_rn(v.x, v.y);
    __half2 h23 = __floats2half2_rn(v.z, v.w);
    uint2 r;
    r.x = *(uint32_t*)&h01;
    r.y = *(uint32_t*)&h23;
    return r;
}

// ---------------- init + prepass ----------------
__global__ void init_kernel() {
    if (threadIdx.x < N_EXP) g_counts[threadIdx.x] = 0;
}

__global__ __launch_bounds__(256) void cast_x_kernel(const float* __restrict__ x) {
    int idx = blockIdx.x * 256 + threadIdx.x;   // float4 index
    if (idx < T_TOK * H_DIM / 4) {
        float4 v = ((const float4*)x)[idx];
        ((uint2*)g_xh)[idx] = f4_to_h4(v);
    }
}

// ---------------- router (fp32, unchanged) ----------------
__global__ __launch_bounds__(256) void router_kernel(const float* __restrict__ x,
                                                     const float* __restrict__ gw) {
    int t = blockIdx.x;
    __shared__ float slog[N_EXP];
    if (threadIdx.x < N_EXP) slog[threadIdx.x] = 0.f;
    __syncthreads();

    const float* xr = x + (size_t)t * H_DIM;
    float part[N_EXP];
#pragma unroll
    for (int e = 0; e < N_EXP; e++) part[e] = 0.f;

    for (int h = threadIdx.x; h < H_DIM; h += 256) {
        float xv = xr[h];
#pragma unroll
        for (int e = 0; e < N_EXP; e++) part[e] += xv * gw[e * H_DIM + h];
    }
#pragma unroll
    for (int e = 0; e < N_EXP; e++) {
#pragma unroll
        for (int off = 16; off; off >>= 1)
            part[e] += __shfl_down_sync(0xFFFFFFFFu, part[e], off);
    }
    if ((threadIdx.x & 31) == 0) {
#pragma unroll
        for (int e = 0; e < N_EXP; e++) atomicAdd(&slog[e], part[e]);
    }
    __syncthreads();

    if (threadIdx.x == 0) {
        float mx = -1e30f;
#pragma unroll
        for (int e = 0; e < N_EXP; e++) mx = fmaxf(mx, slog[e]);
        float p[N_EXP]; float s = 0.f;
#pragma unroll
        for (int e = 0; e < N_EXP; e++) { p[e] = __expf(slog[e] - mx); s += p[e]; }
        float inv = 1.f / s;
#pragma unroll
        for (int e = 0; e < N_EXP; e++) p[e] *= inv;

        int sel[K_TOP]; float wv[K_TOP]; float ws = 0.f;
        bool used[N_EXP];
#pragma unroll
        for (int e = 0; e < N_EXP; e++) used[e] = false;
#pragma unroll
        for (int k = 0; k < K_TOP; k++) {
            int best = -1; float bv = -1.f;
#pragma unroll
            for (int e = 0; e < N_EXP; e++)
                if (!used[e] && p[e] > bv) { bv = p[e]; best = e; }
            used[best] = true; sel[k] = best; wv[k] = bv; ws += bv;
        }
        float wsi = 1.f / ws;
#pragma unroll
        for (int k = 0; k < K_TOP; k++) {
            int e = sel[k];
            int pos = atomicAdd(&g_counts[e], 1);
            g_tokens[e * T_TOK + pos] = t;
            g_slotw[e * T_TOK + pos] = wv[k] * wsi;
        }
    }
}

// Inner product over one BK=32 tile (2 k16 steps); warp tile 64x32.
__device__ __forceinline__ void tile_mma(const __half* sA, const __half* sB,
                                         int wm, int wn, FragC acc[4][2]) {
#pragma unroll
    for (int ks = 0; ks < 2; ks++) {
        FragA a[4];
#pragma unroll
        for (int i = 0; i < 4; i++)
            wmma::load_matrix_sync(a[i], sA + (wm * 64 + i * 16) * LDH + ks * 16, LDH);
#pragma unroll
        for (int j = 0; j < 2; j++) {
            FragB b;
            wmma::load_matrix_sync(b, sB + (wn * 32 + j * 16) * LDH + ks * 16, LDH);
#pragma unroll
            for (int i = 0; i < 4; i++)
                wmma::mma_sync(acc[i][j], a[i], b, acc[i][j]);
        }
    }
}

// ============ GEMM1: gathered g_xh @ [gate||up]^T (fp16), fused SiLU ============
// grid (T/128=8 m FASTEST, F/64=22, 16); 256 thr
__global__ __launch_bounds__(NTHR, 2) void gemm1_kernel(const float* __restrict__ wv1) {
    extern __shared__ __half smem[];
    __shared__ int stok[BM];

    int e = blockIdx.z;
    int ne = g_counts[e];
    int m0 = blockIdx.x * BM;
    if (m0 >= ne) return;
    int n0 = blockIdx.y * 64;      // f-slice of 64 (B rows: 64 gate + 64 up)

    int tid = threadIdx.x;
    int wid = tid >> 5;
    int wm = wid >> 2;             // 0..1
    int wn = wid & 3;              // 0..3

    for (int i = tid; i < BM; i += NTHR) {
        int gi = m0 + i;
        stok[i] = (gi < ne) ? g_tokens[e * T_TOK + gi] : g_tokens[e * T_TOK + m0];
    }
    __syncthreads();

    // A: 2 x 16B cp.async chunks per thread (128 rows x 32 halfs)
    const __half* pA[2]; uint32_t oA[2];
#pragma unroll
    for (int j = 0; j < 2; j++) {
        int idx = tid + j * NTHR, r = idx >> 2, c = (idx & 3) * 8;
        oA[j] = r * LDH + c;
        pA[j] = g_xh + (size_t)stok[r] * H_DIM + c;
    }
    // B: 4 float4 LDG chunks per thread (128 rows x 32 floats), convert -> half STS
    const float* pB[4]; uint32_t oB[4];
#pragma unroll
    for (int j = 0; j < 4; j++) {
        int idx = tid + j * NTHR, r = idx >> 3, c = (idx & 7) * 4;
        oB[j] = BM * LDH + r * LDH + c;
        size_t row = (r < 64) ? ((size_t)e * 2 * F_DIM + n0 + r)
                              : ((size_t)e * 2 * F_DIM + F_DIM + n0 + (r - 64));
        pB[j] = wv1 + row * H_DIM + c;
    }

#define A_ISSUE(s) do {                                                           \
    __half* st_ = smem + (s) * STG_HALFS;                                         \
    _Pragma("unroll")                                                             \
    for (int j_ = 0; j_ < 2; j_++) { cp16(st_ + oA[j_], pA[j_]); pA[j_] += BK; }  \
    CP_COMMIT();                                                                  \
} while (0)
#define B_STORE(s, v) do {                                                        \
    __half* st_ = smem + (s) * STG_HALFS;                                         \
    _Pragma("unroll")                                                             \
    for (int j_ = 0; j_ < 4; j_++) *(uint2*)(st_ + oB[j_]) = f4_to_h4(v[j_]);     \
} while (0)

    FragC acc[4][2];
#pragma unroll
    for (int i = 0; i < 4; i++)
#pragma unroll
        for (int j = 0; j < 2; j++) wmma::fill_fragment(acc[i][j], 0.f);

    const int NT = H_DIM / BK;     // 64
    // prologue: A groups + blocking B for stages 0..2
    A_ISSUE(0); A_ISSUE(1); A_ISSUE(2);
#pragma unroll
    for (int s = 0; s < 3; s++) {
        float4 v[4];
#pragma unroll
        for (int j = 0; j < 4; j++) { v[j] = *(const float4*)pB[j]; pB[j] += BK; }
        B_STORE(s, v);
    }

    int scons = 0, sprod = 3;
    for (int it = 0; it < NT; ++it) {
        float4 vB[4];
        bool pf = (it + 3 < NT);
        if (pf) {
#pragma unroll
            for (int j = 0; j < 4; j++) { vB[j] = *(const float4*)pB[j]; pB[j] += BK; }
        }
        if (it + 3 < NT + 3 - 1) {}   // (no-op; keep structure simple)
        CP_WAIT2();
        __syncthreads();
        if (pf) A_ISSUE(sprod);

        const __half* sA = smem + scons * STG_HALFS;
        tile_mma(sA, sA + BM * LDH, wm, wn, acc);

        if (pf) B_STORE(sprod, vB);
        if (++sprod == NSTAGE) sprod = 0;
        if (++scons == NSTAGE) scons = 0;
    }
#undef A_ISSUE
#undef B_STORE

    // epilogue: fp32 stage 128x132 (cols 0..63 gate, 64..127 up), SiLU -> g_acth (half)
    __syncthreads();
    float* stage = (float*)smem;
#pragma unroll
    for (int i = 0; i < 4; i++)
#pragma unroll
        for (int j = 0; j < 2; j++)
            wmma::store_matrix_sync(stage + (wm * 64 + i * 16) * LDSTG + wn * 32 + j * 16,
                                    acc[i][j], LDSTG, wmma::mem_row_major);
    __syncthreads();

    for (int q = tid; q < BM * 16; q += NTHR) {
        int r = q >> 4, c = (q & 15) * 4;   // gate cols 0..60
        int gr = m0 + r;
        if (gr < ne) {
            float4 g = *(float4*)(stage + r * LDSTG + c);
            float4 u = *(float4*)(stage + r * LDSTG + 64 + c);
            float4 o;
            o.x = (g.x / (1.f + __expf(-g.x))) * u.x;
            o.y = (g.y / (1.f + __expf(-g.y))) * u.y;
            o.z = (g.z / (1.f + __expf(-g.z))) * u.z;
            o.w = (g.w / (1.f + __expf(-g.w))) * u.w;
            *(uint2*)(g_acth + ((size_t)e * T_TOK + gr) * F_DIM + n0 + c) = f4_to_h4(o);
        }
    }
}

// ============ GEMM2: g_acth @ w2^T (fp16), fused weighted atomic combine ============
// grid (T/128=8 m FASTEST, H/128=16, 16); 256 thr
__global__ __launch_bounds__(NTHR, 2) void gemm2_kernel(const float* __restrict__ w2,
                                                        float* __restrict__ out) {
    extern __shared__ __half smem[];
    __shared__ int   stok[BM];
    __shared__ float swt[BM];

    int e = blockIdx.z;
    int ne = g_counts[e];
    int m0 = blockIdx.x * BM;
    if (m0 >= ne) return;
    int n0 = blockIdx.y * BN;

    int tid = threadIdx.x;
    int wid = tid >> 5;
    int wm = wid >> 2;
    int wn = wid & 3;
    int nrows = ne - m0;

    for (int i = tid; i < BM; i += NTHR) {
        bool ok = (m0 + i < ne);
        stok[i] = ok ? g_tokens[e * T_TOK + m0 + i] : 0;
        swt[i]  = ok ? g_slotw[e * T_TOK + m0 + i] : 0.f;
    }
    __syncthreads();

    const __half* pA[2]; uint32_t oA[2];
#pragma unroll
    for (int j = 0; j < 2; j++) {
        int idx = tid + j * NTHR, r = idx >> 2, c = (idx & 3) * 8;
        oA[j] = r * LDH + c;
        int rr = (r < nrows) ? r : 0;
        pA[j] = g_acth + ((size_t)e * T_TOK + m0 + rr) * F_DIM + c;
    }
    const float* pB[4]; uint32_t oB[4];
#pragma unroll
    for (int j = 0; j < 4; j++) {
        int idx = tid + j * NTHR, r = idx >> 3, c = (idx & 7) * 4;
        oB[j] = BM * LDH + r * LDH + c;
        pB[j] = w2 + ((size_t)e * H_DIM + n0 + r) * F_DIM + c;
    }

#define A_ISSUE(s) do {                                                           \
    __half* st_ = smem + (s) * STG_HALFS;                                         \
    _Pragma("unroll")                                                             \
    for (int j_ = 0; j_ < 2; j_++) { cp16(st_ + oA[j_], pA[j_]); pA[j_] += BK; }  \
    CP_COMMIT();                                                                  \
} while (0)
#define B_STORE(s, v) do {                                                        \
    __half* st_ = smem + (s) * STG_HALFS;                                         \
    _Pragma("unroll")                                                             \
    for (int j_ = 0; j_ < 4; j_++) *(uint2*)(st_ + oB[j_]) = f4_to_h4(v[j_]);     \
} while (0)

    FragC acc[4][2];
#pragma unroll
    for (int i = 0; i < 4; i++)
#pragma unroll
        for (int j = 0; j < 2; j++) wmma::fill_fragment(acc[i][j], 0.f);

    const int NT = F_DIM / BK;     // 44
    A_ISSUE(0); A_ISSUE(1); A_ISSUE(2);
#pragma unroll
    for (int s = 0; s < 3; s++) {
        float4 v[4];
#pragma unroll
        for (int j = 0; j < 4; j++) { v[j] = *(const float4*)pB[j]; pB[j] += BK; }
        B_STORE(s, v);
    }

    int scons = 0, sprod = 3;
    for (int it = 0; it < NT; ++it) {
        float4 vB[4];
        bool pf = (it + 3 < NT);
        if (pf) {
#pragma unroll
            for (int j = 0; j < 4; j++) { vB[j] = *(const float4*)pB[j]; pB[j] += BK; }
        }
        CP_WAIT2();
        __syncthreads();
        if (pf) A_ISSUE(sprod);

        const __half* sA = smem + scons * STG_HALFS;
        tile_mma(sA, sA + BM * LDH, wm, wn, acc);

        if (pf) B_STORE(sprod, vB);
        if (++sprod == NSTAGE) sprod = 0;
        if (++scons == NSTAGE) scons = 0;
    }
#undef A_ISSUE
#undef B_STORE

    // epilogue: fp32 stage 128x132, weighted atomic scatter to out[t, h]
    __syncthreads();
    float* stage = (float*)smem;
#pragma unroll
    for (int i = 0; i < 4; i++)
#pragma unroll
        for (int j = 0; j < 2; j++)
            wmma::store_matrix_sync(stage + (wm * 64 + i * 16) * LDSTG + wn * 32 + j * 16,
                                    acc[i][j], LDSTG, wmma::mem_row_major);
    __syncthreads();

    for (int idx = tid; idx < BM * 32; idx += NTHR) {
        int r = idx >> 5, cc = (idx & 31) * 4;
        if (r < nrows) {
            int t = stok[r];
            float w = swt[r];
            float4 v = *(float4*)(stage + r * LDSTG + cc);
            float* o = out + (size_t)t * H_DIM + n0 + cc;
            atomicAdd(o + 0, w * v.x);
            atomicAdd(o + 1, w * v.y);
            atomicAdd(o + 2, w * v.z);
            atomicAdd(o + 3, w * v.w);
        }
    }
}

// ---------------- launch ----------------
extern "C" void kernel_launch(void* const* d_in, const int* in_sizes, int n_in,
                              void* d_out, int out_size) {
    (void)in_sizes; (void)n_in;
    const float* x    = (const float*)d_in[0];
    const float* gw   = (const float*)d_in[1];
    const float* wv1  = (const float*)d_in[2];
    const float* w2   = (const float*)d_in[3];
    float* out = (float*)d_out;

    static bool attr_set = false;
    if (!attr_set) {
        cudaFuncSetAttribute(gemm1_kernel, cudaFuncAttributeMaxDynamicSharedMemorySize, SMEM_BYTES);
        cudaFuncSetAttribute(gemm2_kernel, cudaFuncAttributeMaxDynamicSharedMemorySize, SMEM_BYTES);
        attr_set = true;
    }

    cudaMemsetAsync(out, 0, (size_t)out_size * sizeof(float));
    init_kernel<<<1, 32>>>();
    cast_x_kernel<<<(T_TOK * H_DIM / 4 + 255) / 256, 256>>>(x);
    router_kernel<<<T_TOK, 256>>>(x, gw);
    gemm1_kernel<<<dim3(T_TOK / BM, F_DIM / 64, N_EXP), NTHR, SMEM_BYTES>>>(wv1);
    gemm2_kernel<<<dim3(T_TOK / BM, H_DIM / BN, N_EXP), NTHR, SMEM_BYTES>>>(w2, out);
}